// round 16
// baseline (speedup 1.0000x reference)
#include <cuda_runtime.h>
#include <cuda_bf16.h>
#include <cuda_fp16.h>
#include <cstdint>
#include <math.h>

// Problem constants (B=4, T=8192, D=2048, E=64, top-k=8)
constexpr int M_TOT = 32768;
constexpr int DDIM  = 2048;
constexpr int NEXP  = 64;
constexpr int TOPK  = 8;

#define CTAM     128            // tokens per CTA (2 CTAs/SM)
#define KC       32             // k per chunk (fp16 -> 64B rows, SW64)
#define NCHUNK   (DDIM / KC)    // 64
#define RTHREADS 256

// Flag threshold (relative to p_max). fp16 2-product split drops x*w_lo:
// logit error sigma ~1.6e-4 abs -> p-gap noise ~2.3e-4*p; 1.2e-3 ~ 7 sigma.
// All knife-edge tokens land in the exact (Kahan) rescue kernel.
#define FLAG_TAU 1.2e-3f

// ---------------- device globals (no runtime allocation allowed) ----------------
__device__ int g_flag_count;
__device__ int g_flag_list[M_TOT];
// w rounded to fp16, TRANSPOSED to [n][k] (K-major rows).
__device__ __align__(16) __half g_w_h[NEXP * DDIM];

// ---------------- helpers ----------------
__device__ __forceinline__ uint32_t smem_to_u32(const void* p) {
    uint32_t a;
    asm("{ .reg .u64 t; cvta.to.shared.u64 t, %1; cvt.u32.u64 %0, t; }" : "=r"(a) : "l"(p));
    return a;
}
// SW64 swizzle: XOR 16B-unit index (bits[4:6)) with (row>>1)&3 (bits[7:9)).
// Conflict-free for 8-row x 16B ldmatrix reads on 64B-row tiles.
#define SWZ(o) ((o) ^ (((o) >> 3) & 0x30))

__device__ __forceinline__ void ldmatrix_x4(uint32_t* r, uint32_t addr) {
    asm volatile("ldmatrix.sync.aligned.m8n8.x4.shared.b16 {%0,%1,%2,%3}, [%4];"
                 : "=r"(r[0]), "=r"(r[1]), "=r"(r[2]), "=r"(r[3]) : "r"(addr));
}
__device__ __forceinline__ void mma_fp16(float* d, const uint32_t* a,
                                         uint32_t b0, uint32_t b1) {
    asm volatile(
        "mma.sync.aligned.m16n8k16.row.col.f32.f16.f16.f32 "
        "{%0,%1,%2,%3}, {%4,%5,%6,%7}, {%8,%9}, {%0,%1,%2,%3};"
        : "+f"(d[0]), "+f"(d[1]), "+f"(d[2]), "+f"(d[3])
        : "r"(a[0]), "r"(a[1]), "r"(a[2]), "r"(a[3]), "r"(b0), "r"(b1));
}
// split two fp32 into packed fp16 hi pair + fp16 residual pair
__device__ __forceinline__ void split2h(float a, float b, uint32_t& hi, uint32_t& lo) {
    __half h0 = __float2half_rn(a), h1 = __float2half_rn(b);
    __half l0 = __float2half_rn(a - __half2float(h0));
    __half l1 = __float2half_rn(b - __half2float(h1));
    hi = (uint32_t)__half_as_ushort(h0) | ((uint32_t)__half_as_ushort(h1) << 16);
    lo = (uint32_t)__half_as_ushort(l0) | ((uint32_t)__half_as_ushort(l1) << 16);
}

// ---------------- shared epilogue (proven rounds 12/14/15) ----------------
template <int R>
__device__ __forceinline__ void softmax_topk(float v0, float v1, int lane,
                                             float* wsel, int* isel) {
    const float NEG_INF = __int_as_float(0xff800000);
    float mx = fmaxf(v0, v1);
#pragma unroll
    for (int o = 16; o; o >>= 1) mx = fmaxf(mx, __shfl_xor_sync(0xffffffffu, mx, o));
    float e0 = expf(v0 - mx), e1 = expf(v1 - mx);
    float s = e0 + e1;
#pragma unroll
    for (int o = 16; o; o >>= 1) s += __shfl_xor_sync(0xffffffffu, s, o);
    float p0 = __fdiv_rn(e0, s);
    float p1 = __fdiv_rn(e1, s);
#pragma unroll
    for (int r = 0; r < R; r++) {
        float cv; int ci;
        if (p1 > p0) { cv = p1; ci = lane + 32; }
        else         { cv = p0; ci = lane; }
#pragma unroll
        for (int o = 16; o; o >>= 1) {
            float ov = __shfl_xor_sync(0xffffffffu, cv, o);
            int   oi = __shfl_xor_sync(0xffffffffu, ci, o);
            if (ov > cv || (ov == cv && oi < ci)) { cv = ov; ci = oi; }
        }
        wsel[r] = cv; isel[r] = ci;
        if (ci == lane)           p0 = NEG_INF;
        else if (ci == lane + 32) p1 = NEG_INF;
    }
}

__device__ __forceinline__ void store_token(const float* wsel, const int* isel,
                                            int tg, float* out) {
    float mw = wsel[0];
    float es[TOPK];
    float se = 0.0f;
#pragma unroll
    for (int r = 0; r < TOPK; r++) { es[r] = expf(wsel[r] - mw); se += es[r]; }
    float* ow = out + (size_t)tg * TOPK;
    float* oe = out + (size_t)M_TOT * TOPK + (size_t)tg * TOPK;
#pragma unroll
    for (int r = 0; r < TOPK; r++) {
        ow[r] = __fdiv_rn(es[r], se);
        oe[r] = (float)isel[r];
    }
}

// ---------------- kernel A: prep — round w to fp16 [n][k]; reset flags ----------------
__global__ void prep_w_kernel(const float* __restrict__ w) {
    int i = blockIdx.x * blockDim.x + threadIdx.x;
    if (i == 0) g_flag_count = 0;
    if (i < DDIM * NEXP) {
        int k = i >> 6;          // w is [k][n]
        int n = i & 63;
        g_w_h[n * DDIM + k] = __float2half_rn(w[i]);
    }
}

// ---------------- kernel B: HMMA fp16 2-product router ----------------
// Stage (20480 B): A_hi @0 (8K), A_lo @8192 (8K), B_h @16384 (4K).
// Two stages = 40960 B. Epilogue reuses [0, 128*66*4 = 33792) as Lg fp32.
#define STAGE_BYTES 20480
#define ROUTER_SMEM (2 * STAGE_BYTES)
#define LG_STRIDE 66

__global__ __launch_bounds__(RTHREADS, 2)
void router_hmma_kernel(const float* __restrict__ x, float* __restrict__ out) {
    extern __shared__ char dsm[];
    const int tid  = threadIdx.x;
    const int wid  = tid >> 5;
    const int lane = tid & 31;
    const int m0   = blockIdx.x * CTAM;

    const int bn   = tid >> 2;          // B loader: expert row (0..63)
    const int bcu  = tid & 3;           // B loader: 16B unit (0..3)

    // accumulators: 1 m-tile x 8 n-tiles x 4 regs
    float acc[8][4];
#pragma unroll
    for (int i = 0; i < 8; i++)
#pragma unroll
        for (int q = 0; q < 4; q++) acc[i][q] = 0.0f;

    // ---- prologue: prefetch chunk 0 into registers ----
    float4 xa[4];
    uint4  bhv;
#pragma unroll
    for (int j = 0; j < 4; j++) {
        int s = tid + j * RTHREADS;       // 0..1023
        int tok = s >> 3, kq = s & 7;     // 128 tok x 8 float4
        xa[j] = *(const float4*)(x + (size_t)(m0 + tok) * DDIM + kq * 4);
    }
    bhv = *(const uint4*)((const char*)g_w_h + (size_t)bn * DDIM * 2 + bcu * 16);

    const int grp = lane >> 3, r8 = lane & 7;

    for (int c = 0; c < NCHUNK; c++) {
        char* base = dsm + (c & 1) * STAGE_BYTES;

        // ---- STS: split-convert A (fp16 hi/lo), copy B (swizzled) ----
#pragma unroll
        for (int j = 0; j < 4; j++) {
            int s = tid + j * RTHREADS;
            int tok = s >> 3, kq = s & 7;
            uint2 hp, lp;
            split2h(xa[j].x, xa[j].y, hp.x, lp.x);
            split2h(xa[j].z, xa[j].w, hp.y, lp.y);
            uint32_t off = tok * 64 + kq * 8;
            uint32_t sw  = SWZ(off);
            *(uint2*)(base +        sw) = hp;
            *(uint2*)(base + 8192 + sw) = lp;
        }
        {
            uint32_t off = bn * 64 + bcu * 16;
            uint32_t sw  = SWZ(off);
            *(uint4*)(base + 16384 + sw) = bhv;
        }
        __syncthreads();

        // ---- prefetch chunk c+1 (overlaps with MMA below) ----
        if (c + 1 < NCHUNK) {
#pragma unroll
            for (int j = 0; j < 4; j++) {
                int s = tid + j * RTHREADS;
                int tok = s >> 3, kq = s & 7;
                xa[j] = *(const float4*)(x + (size_t)(m0 + tok) * DDIM
                                           + (c + 1) * KC + kq * 4);
            }
            bhv = *(const uint4*)((const char*)g_w_h + (size_t)bn * DDIM * 2
                                  + (c + 1) * 64 + bcu * 16);
        }

        // ---- MMA: 2 k16-steps, 2 products (hi*w + lo*w) ----
        uint32_t sA = smem_to_u32(base);
        uint32_t sB = sA + 16384;
#pragma unroll
        for (int s = 0; s < 2; s++) {
            uint32_t a_hi[4], a_lo[4];
            {
                int arow  = wid * 16 + ((grp & 1) << 3) + r8;
                int aunit = s * 2 + (grp >> 1);
                uint32_t aoff = SWZ((uint32_t)(arow * 64 + aunit * 16));
                ldmatrix_x4(a_hi, sA + aoff);
                ldmatrix_x4(a_lo, sA + 8192 + aoff);
            }
#pragma unroll
            for (int i = 0; i < 4; i++) {          // n-tile pairs (2i, 2i+1)
                int brow  = i * 16 + ((grp >> 1) << 3) + r8;
                int bunit = s * 2 + (grp & 1);
                uint32_t boff = SWZ((uint32_t)(brow * 64 + bunit * 16));
                uint32_t bh[4];
                ldmatrix_x4(bh, sB + boff);
                mma_fp16(acc[2 * i],     a_hi, bh[0], bh[1]);
                mma_fp16(acc[2 * i],     a_lo, bh[0], bh[1]);
                mma_fp16(acc[2 * i + 1], a_hi, bh[2], bh[3]);
                mma_fp16(acc[2 * i + 1], a_lo, bh[2], bh[3]);
            }
        }
        // single barrier per iter: stage written at c+2 was last read at c,
        // separated by sync(c+1) which all warps pass only after MMA(c).
    }

    // ---- fragments -> Lg[128][66] fp32 ----
    __syncthreads();
    float* Lg = (float*)dsm;
    {
        int r  = wid * 16 + (lane >> 2);
        int cb = (lane & 3) * 2;
#pragma unroll
        for (int i = 0; i < 8; i++) {
            *(float2*)&Lg[r * LG_STRIDE + i * 8 + cb] =
                make_float2(acc[i][0], acc[i][1]);
            *(float2*)&Lg[(r + 8) * LG_STRIDE + i * 8 + cb] =
                make_float2(acc[i][2], acc[i][3]);
        }
    }
    __syncthreads();

    // ---- softmax(64) -> top-9 -> flag -> softmax(8) -> store ----
    for (int tt = 0; tt < 16; tt++) {
        const int t = wid * 16 + tt;
        float v0 = Lg[t * LG_STRIDE + lane];
        float v1 = Lg[t * LG_STRIDE + 32 + lane];
        float wsel[TOPK + 1];
        int   isel[TOPK + 1];
        softmax_topk<TOPK + 1>(v0, v1, lane, wsel, isel);
        if (lane == 0) {
            const int tg = m0 + t;
            bool flag = false;
            float tau = wsel[0] * FLAG_TAU;
#pragma unroll
            for (int r = 0; r < TOPK; r++)
                if (wsel[r] - wsel[r + 1] <= tau) flag = true;
            if (flag) {
                int slot = atomicAdd(&g_flag_count, 1);
                g_flag_list[slot] = tg;
            }
            store_token(wsel, isel, tg, out);
        }
    }
}

// ---------------- kernel C: exact (Kahan) recompute of flagged tokens ----------------
__global__ __launch_bounds__(256)
void exact_fix_kernel(const float* __restrict__ x,
                      const float* __restrict__ w,
                      float* __restrict__ out) {
    __shared__ float sx[DDIM];
    __shared__ float ss[256], sc[256];
    __shared__ float slog[NEXP];

    const int tid = threadIdx.x;
    const int n = g_flag_count;

    for (int i = blockIdx.x; i < n; i += gridDim.x) {
        const int t = g_flag_list[i];
        for (int j = tid; j < DDIM; j += 256)
            sx[j] = x[(size_t)t * DDIM + j];
        __syncthreads();

        const int e   = tid >> 2;
        const int sub = tid & 3;
        float s = 0.0f, c = 0.0f;
        const int k0 = sub * (DDIM / 4);
#pragma unroll 8
        for (int k = k0; k < k0 + DDIM / 4; k++) {
            float p = __fmul_rn(sx[k], w[(size_t)k * NEXP + e]);
            float y = __fsub_rn(p, c);
            float tt = __fadd_rn(s, y);
            c = __fsub_rn(__fsub_rn(tt, s), y);
            s = tt;
        }
        ss[tid] = s; sc[tid] = c;
        __syncthreads();

        if (tid < NEXP) {
            double d = 0.0;
#pragma unroll
            for (int q = 0; q < 4; q++)
                d += (double)ss[tid * 4 + q] - (double)sc[tid * 4 + q];
            slog[tid] = (float)d;
        }
        __syncthreads();

        if (tid < 32) {
            float v0 = slog[tid];
            float v1 = slog[tid + 32];
            float wsel[TOPK];
            int   isel[TOPK];
            softmax_topk<TOPK>(v0, v1, tid, wsel, isel);
            if (tid == 0) store_token(wsel, isel, t, out);
        }
        __syncthreads();
    }
}

extern "C" void kernel_launch(void* const* d_in, const int* in_sizes, int n_in,
                              void* d_out, int out_size) {
    const float* x = nullptr;
    const float* w = nullptr;
    for (int i = 0; i < n_in; i++) {
        if (in_sizes[i] == M_TOT * DDIM)      x = (const float*)d_in[i];
        else if (in_sizes[i] == DDIM * NEXP)  w = (const float*)d_in[i];
    }
    float* out = (float*)d_out;

    cudaFuncSetAttribute(router_hmma_kernel,
                         cudaFuncAttributeMaxDynamicSharedMemorySize, ROUTER_SMEM);

    prep_w_kernel<<<(DDIM * NEXP + 255) / 256, 256>>>(w);
    router_hmma_kernel<<<M_TOT / CTAM, RTHREADS, ROUTER_SMEM>>>(x, out);
    exact_fix_kernel<<<2048, 256>>>(x, w, out);
}

// round 17
// speedup vs baseline: 1.2873x; 1.2873x over previous
#include <cuda_runtime.h>
#include <cuda_bf16.h>
#include <cuda_fp16.h>
#include <cstdint>
#include <math.h>

// Problem constants (B=4, T=8192, D=2048, E=64, top-k=8)
constexpr int M_TOT = 32768;
constexpr int DDIM  = 2048;
constexpr int NEXP  = 64;
constexpr int TOPK  = 8;

#define CTAM     128            // tokens per CTA (2 CTAs/SM)
#define KC       32             // k per chunk (fp16 -> 64B rows, SW64)
#define NCHUNK   (DDIM / KC)    // 64
#define RTHREADS 256

// A_lo stored pre-scaled by 2^10 (exact) to keep all residuals in fp16
// normal range; folded back with LO_SCALE_INV at the epilogue.
#define LO_SCALE     1024.0f
#define LO_SCALE_INV (1.0f / 1024.0f)

// Flag threshold (relative to p_max). fp16 2-product drops x*w_lo:
// logit noise ~1.1e-4 abs -> p-gap noise ~1.6e-4*p_max; 8e-4 ~ 5 sigma.
// All knife-edge tokens land in the exact (Kahan) rescue kernel.
#define FLAG_TAU 8e-4f

// ---------------- device globals (no runtime allocation allowed) ----------------
__device__ int g_flag_count;
__device__ int g_flag_list[M_TOT];
// w rounded to fp16, TRANSPOSED to [n][k] (K-major rows).
__device__ __align__(16) __half g_w_h[NEXP * DDIM];

// ---------------- helpers ----------------
__device__ __forceinline__ uint32_t smem_to_u32(const void* p) {
    uint32_t a;
    asm("{ .reg .u64 t; cvta.to.shared.u64 t, %1; cvt.u32.u64 %0, t; }" : "=r"(a) : "l"(p));
    return a;
}
// SW64 swizzle: XOR 16B-unit index (bits[4:6)) with (row>>1)&3 (bits[7:9)).
#define SWZ(o) ((o) ^ (((o) >> 3) & 0x30))

__device__ __forceinline__ void ldmatrix_x4(uint32_t* r, uint32_t addr) {
    asm volatile("ldmatrix.sync.aligned.m8n8.x4.shared.b16 {%0,%1,%2,%3}, [%4];"
                 : "=r"(r[0]), "=r"(r[1]), "=r"(r[2]), "=r"(r[3]) : "r"(addr));
}
__device__ __forceinline__ void mma_fp16(float* d, const uint32_t* a,
                                         uint32_t b0, uint32_t b1) {
    asm volatile(
        "mma.sync.aligned.m16n8k16.row.col.f32.f16.f16.f32 "
        "{%0,%1,%2,%3}, {%4,%5,%6,%7}, {%8,%9}, {%0,%1,%2,%3};"
        : "+f"(d[0]), "+f"(d[1]), "+f"(d[2]), "+f"(d[3])
        : "r"(a[0]), "r"(a[1]), "r"(a[2]), "r"(a[3]), "r"(b0), "r"(b1));
}
// split two fp32 into packed fp16 hi pair + SCALED fp16 residual pair
__device__ __forceinline__ void split2h(float a, float b, uint32_t& hi, uint32_t& lo) {
    __half h0 = __float2half_rn(a), h1 = __float2half_rn(b);
    __half l0 = __float2half_rn((a - __half2float(h0)) * LO_SCALE);
    __half l1 = __float2half_rn((b - __half2float(h1)) * LO_SCALE);
    hi = (uint32_t)__half_as_ushort(h0) | ((uint32_t)__half_as_ushort(h1) << 16);
    lo = (uint32_t)__half_as_ushort(l0) | ((uint32_t)__half_as_ushort(l1) << 16);
}

// ---------------- shared epilogue (proven rounds 12/14/15) ----------------
template <int R>
__device__ __forceinline__ void softmax_topk(float v0, float v1, int lane,
                                             float* wsel, int* isel) {
    const float NEG_INF = __int_as_float(0xff800000);
    float mx = fmaxf(v0, v1);
#pragma unroll
    for (int o = 16; o; o >>= 1) mx = fmaxf(mx, __shfl_xor_sync(0xffffffffu, mx, o));
    float e0 = expf(v0 - mx), e1 = expf(v1 - mx);
    float s = e0 + e1;
#pragma unroll
    for (int o = 16; o; o >>= 1) s += __shfl_xor_sync(0xffffffffu, s, o);
    float p0 = __fdiv_rn(e0, s);
    float p1 = __fdiv_rn(e1, s);
#pragma unroll
    for (int r = 0; r < R; r++) {
        float cv; int ci;
        if (p1 > p0) { cv = p1; ci = lane + 32; }
        else         { cv = p0; ci = lane; }
#pragma unroll
        for (int o = 16; o; o >>= 1) {
            float ov = __shfl_xor_sync(0xffffffffu, cv, o);
            int   oi = __shfl_xor_sync(0xffffffffu, ci, o);
            if (ov > cv || (ov == cv && oi < ci)) { cv = ov; ci = oi; }
        }
        wsel[r] = cv; isel[r] = ci;
        if (ci == lane)           p0 = NEG_INF;
        else if (ci == lane + 32) p1 = NEG_INF;
    }
}

__device__ __forceinline__ void store_token(const float* wsel, const int* isel,
                                            int tg, float* out) {
    float mw = wsel[0];
    float es[TOPK];
    float se = 0.0f;
#pragma unroll
    for (int r = 0; r < TOPK; r++) { es[r] = expf(wsel[r] - mw); se += es[r]; }
    float* ow = out + (size_t)tg * TOPK;
    float* oe = out + (size_t)M_TOT * TOPK + (size_t)tg * TOPK;
#pragma unroll
    for (int r = 0; r < TOPK; r++) {
        ow[r] = __fdiv_rn(es[r], se);
        oe[r] = (float)isel[r];
    }
}

// ---------------- kernel A: prep — round w to fp16 [n][k]; reset flags ----------------
__global__ void prep_w_kernel(const float* __restrict__ w) {
    int i = blockIdx.x * blockDim.x + threadIdx.x;
    if (i == 0) g_flag_count = 0;
    if (i < DDIM * NEXP) {
        int k = i >> 6;          // w is [k][n]
        int n = i & 63;
        g_w_h[n * DDIM + k] = __float2half_rn(w[i]);
    }
}

// ---------------- kernel B: HMMA fp16 2-product router (denormal-free lo) ----------------
// Stage (20480 B): A_hi @0 (8K), A_lo @8192 (8K), B_h @16384 (4K).
// Two stages = 40960 B. Epilogue reuses [0, 128*66*4 = 33792) as Lg fp32.
#define STAGE_BYTES 20480
#define ROUTER_SMEM (2 * STAGE_BYTES)
#define LG_STRIDE 66

__global__ __launch_bounds__(RTHREADS, 2)
void router_hmma_kernel(const float* __restrict__ x, float* __restrict__ out) {
    extern __shared__ char dsm[];
    const int tid  = threadIdx.x;
    const int wid  = tid >> 5;
    const int lane = tid & 31;
    const int m0   = blockIdx.x * CTAM;

    const int bn   = tid >> 2;          // B loader: expert row (0..63)
    const int bcu  = tid & 3;           // B loader: 16B unit (0..3)

    // separate hi/lo accumulators (lo is scaled by 2^10)
    float acch[8][4], accl[8][4];
#pragma unroll
    for (int i = 0; i < 8; i++)
#pragma unroll
        for (int q = 0; q < 4; q++) { acch[i][q] = 0.0f; accl[i][q] = 0.0f; }

    // ---- prologue: prefetch chunk 0 into registers ----
    float4 xa[4];
    uint4  bhv;
#pragma unroll
    for (int j = 0; j < 4; j++) {
        int s = tid + j * RTHREADS;       // 0..1023
        int tok = s >> 3, kq = s & 7;     // 128 tok x 8 float4
        xa[j] = *(const float4*)(x + (size_t)(m0 + tok) * DDIM + kq * 4);
    }
    bhv = *(const uint4*)((const char*)g_w_h + (size_t)bn * DDIM * 2 + bcu * 16);

    const int grp = lane >> 3, r8 = lane & 7;

    for (int c = 0; c < NCHUNK; c++) {
        char* base = dsm + (c & 1) * STAGE_BYTES;

        // ---- STS: split-convert A (fp16 hi / scaled lo), copy B (swizzled) ----
#pragma unroll
        for (int j = 0; j < 4; j++) {
            int s = tid + j * RTHREADS;
            int tok = s >> 3, kq = s & 7;
            uint2 hp, lp;
            split2h(xa[j].x, xa[j].y, hp.x, lp.x);
            split2h(xa[j].z, xa[j].w, hp.y, lp.y);
            uint32_t off = tok * 64 + kq * 8;
            uint32_t sw  = SWZ(off);
            *(uint2*)(base +        sw) = hp;
            *(uint2*)(base + 8192 + sw) = lp;
        }
        {
            uint32_t off = bn * 64 + bcu * 16;
            uint32_t sw  = SWZ(off);
            *(uint4*)(base + 16384 + sw) = bhv;
        }
        __syncthreads();

        // ---- prefetch chunk c+1 (overlaps with MMA below) ----
        if (c + 1 < NCHUNK) {
#pragma unroll
            for (int j = 0; j < 4; j++) {
                int s = tid + j * RTHREADS;
                int tok = s >> 3, kq = s & 7;
                xa[j] = *(const float4*)(x + (size_t)(m0 + tok) * DDIM
                                           + (c + 1) * KC + kq * 4);
            }
            bhv = *(const uint4*)((const char*)g_w_h + (size_t)bn * DDIM * 2
                                  + (c + 1) * 64 + bcu * 16);
        }

        // ---- MMA: 2 k16-steps, hi->acch, lo->accl ----
        uint32_t sA = smem_to_u32(base);
        uint32_t sB = sA + 16384;
#pragma unroll
        for (int s = 0; s < 2; s++) {
            uint32_t a_hi[4], a_lo[4];
            {
                int arow  = wid * 16 + ((grp & 1) << 3) + r8;
                int aunit = s * 2 + (grp >> 1);
                uint32_t aoff = SWZ((uint32_t)(arow * 64 + aunit * 16));
                ldmatrix_x4(a_hi, sA + aoff);
                ldmatrix_x4(a_lo, sA + 8192 + aoff);
            }
#pragma unroll
            for (int i = 0; i < 4; i++) {          // n-tile pairs (2i, 2i+1)
                int brow  = i * 16 + ((grp >> 1) << 3) + r8;
                int bunit = s * 2 + (grp & 1);
                uint32_t boff = SWZ((uint32_t)(brow * 64 + bunit * 16));
                uint32_t bh[4];
                ldmatrix_x4(bh, sB + boff);
                mma_fp16(acch[2 * i],     a_hi, bh[0], bh[1]);
                mma_fp16(accl[2 * i],     a_lo, bh[0], bh[1]);
                mma_fp16(acch[2 * i + 1], a_hi, bh[2], bh[3]);
                mma_fp16(accl[2 * i + 1], a_lo, bh[2], bh[3]);
            }
        }
        // single barrier per iter: stage written at c+2 was last read at c,
        // separated by sync(c+1) which all warps pass only after MMA(c).
    }

    // ---- combine hi + lo*2^-10, fragments -> Lg[128][66] fp32 ----
    __syncthreads();
    float* Lg = (float*)dsm;
    {
        int r  = wid * 16 + (lane >> 2);
        int cb = (lane & 3) * 2;
#pragma unroll
        for (int i = 0; i < 8; i++) {
            float v0 = acch[i][0] + accl[i][0] * LO_SCALE_INV;
            float v1 = acch[i][1] + accl[i][1] * LO_SCALE_INV;
            float v2 = acch[i][2] + accl[i][2] * LO_SCALE_INV;
            float v3 = acch[i][3] + accl[i][3] * LO_SCALE_INV;
            *(float2*)&Lg[r * LG_STRIDE + i * 8 + cb]       = make_float2(v0, v1);
            *(float2*)&Lg[(r + 8) * LG_STRIDE + i * 8 + cb] = make_float2(v2, v3);
        }
    }
    __syncthreads();

    // ---- softmax(64) -> top-9 -> flag -> softmax(8) -> store ----
    for (int tt = 0; tt < 16; tt++) {
        const int t = wid * 16 + tt;
        float v0 = Lg[t * LG_STRIDE + lane];
        float v1 = Lg[t * LG_STRIDE + 32 + lane];
        float wsel[TOPK + 1];
        int   isel[TOPK + 1];
        softmax_topk<TOPK + 1>(v0, v1, lane, wsel, isel);
        if (lane == 0) {
            const int tg = m0 + t;
            bool flag = false;
            float tau = wsel[0] * FLAG_TAU;
#pragma unroll
            for (int r = 0; r < TOPK; r++)
                if (wsel[r] - wsel[r + 1] <= tau) flag = true;
            if (flag) {
                int slot = atomicAdd(&g_flag_count, 1);
                g_flag_list[slot] = tg;
            }
            store_token(wsel, isel, tg, out);
        }
    }
}

// ---------------- kernel C: exact (Kahan) recompute of flagged tokens ----------------
__global__ __launch_bounds__(256)
void exact_fix_kernel(const float* __restrict__ x,
                      const float* __restrict__ w,
                      float* __restrict__ out) {
    __shared__ float sx[DDIM];
    __shared__ float ss[256], sc[256];
    __shared__ float slog[NEXP];

    const int tid = threadIdx.x;
    const int n = g_flag_count;

    for (int i = blockIdx.x; i < n; i += gridDim.x) {
        const int t = g_flag_list[i];
        for (int j = tid; j < DDIM; j += 256)
            sx[j] = x[(size_t)t * DDIM + j];
        __syncthreads();

        const int e   = tid >> 2;
        const int sub = tid & 3;
        float s = 0.0f, c = 0.0f;
        const int k0 = sub * (DDIM / 4);
#pragma unroll 8
        for (int k = k0; k < k0 + DDIM / 4; k++) {
            float p = __fmul_rn(sx[k], w[(size_t)k * NEXP + e]);
            float y = __fsub_rn(p, c);
            float tt = __fadd_rn(s, y);
            c = __fsub_rn(__fsub_rn(tt, s), y);
            s = tt;
        }
        ss[tid] = s; sc[tid] = c;
        __syncthreads();

        if (tid < NEXP) {
            double d = 0.0;
#pragma unroll
            for (int q = 0; q < 4; q++)
                d += (double)ss[tid * 4 + q] - (double)sc[tid * 4 + q];
            slog[tid] = (float)d;
        }
        __syncthreads();

        if (tid < 32) {
            float v0 = slog[tid];
            float v1 = slog[tid + 32];
            float wsel[TOPK];
            int   isel[TOPK];
            softmax_topk<TOPK>(v0, v1, tid, wsel, isel);
            if (tid == 0) store_token(wsel, isel, t, out);
        }
        __syncthreads();
    }
}

extern "C" void kernel_launch(void* const* d_in, const int* in_sizes, int n_in,
                              void* d_out, int out_size) {
    const float* x = nullptr;
    const float* w = nullptr;
    for (int i = 0; i < n_in; i++) {
        if (in_sizes[i] == M_TOT * DDIM)      x = (const float*)d_in[i];
        else if (in_sizes[i] == DDIM * NEXP)  w = (const float*)d_in[i];
    }
    float* out = (float*)d_out;

    cudaFuncSetAttribute(router_hmma_kernel,
                         cudaFuncAttributeMaxDynamicSharedMemorySize, ROUTER_SMEM);

    prep_w_kernel<<<(DDIM * NEXP + 255) / 256, 256>>>(w);
    router_hmma_kernel<<<M_TOT / CTAM, RTHREADS, ROUTER_SMEM>>>(x, out);
    exact_fix_kernel<<<2048, 256>>>(x, w, out);
}